// round 12
// baseline (speedup 1.0000x reference)
#include <cuda_runtime.h>
#include <cuda_fp16.h>
#include <cstdint>

#define N_NODES 50000
#define N_EDGES 800000
#define N_RELS  200
#define D       128
#define D4      (D/4)

#define SCAN_T   1024
#define N_CHUNKS ((N_NODES + SCAN_T - 1) / SCAN_T)   // 49

// Scratch (allocation-free rule: __device__ globals)
__device__ float  g_hn[N_NODES * D];    // h * norm (fp32, GEMM A-operand)
__device__ __half g_hnh[N_NODES * D];   // fp16 mirror for gather (half traffic)
__device__ __half g_rh[N_RELS * D];     // fp16 mirror of r
__device__ float  g_agg[N_NODES * D];   // norm * segment_sum(hn[src]-r[rel], dst)
__device__ int    g_cnt[N_NODES];       // per-dst degree (INVARIANT: zero at entry)
__device__ int    g_off[N_NODES + 1];   // CSR offsets
__device__ int    g_cur[N_NODES];       // running fill cursors
__device__ int    g_ekey[N_EDGES];      // packed (src<<8)|rel, bucketed by dst
__device__ int    g_bsum[64];           // per-chunk sums

// ---------------------------------------------------------------------------
// tf32 helpers (baseline PTX, no 'a' features)
// ---------------------------------------------------------------------------
__device__ __forceinline__ uint32_t f2tf32(float f) {
    uint32_t t;
    asm("cvt.rna.tf32.f32 %0, %1;" : "=r"(t) : "f"(f));
    return t;
}
__device__ __forceinline__ void mma_tf32(float* c, const uint32_t* a, const uint32_t* b) {
    asm volatile(
        "mma.sync.aligned.m16n8k8.row.col.f32.tf32.tf32.f32 "
        "{%0,%1,%2,%3}, {%4,%5,%6,%7}, {%8,%9}, {%0,%1,%2,%3};"
        : "+f"(c[0]), "+f"(c[1]), "+f"(c[2]), "+f"(c[3])
        : "r"(a[0]), "r"(a[1]), "r"(a[2]), "r"(a[3]), "r"(b[0]), "r"(b[1]));
}

__device__ __forceinline__ uint32_t pack_h2(float a, float b) {
    __half2 h = __floats2half2_rn(a, b);
    return *reinterpret_cast<uint32_t*>(&h);
}

// ---------------------------------------------------------------------------
// Kernel 1 (fused): hn = h * norm (fp32 + fp16 mirror); r -> fp16; dst histogram.
// g_cnt is zero on entry (static zero-init at load; k_scan1 resets each run).
// ---------------------------------------------------------------------------
#define PREP_T (N_NODES * D4 / 2)   // 800,000 threads

__global__ void k_prep_hist(const float* __restrict__ h,
                            const float* __restrict__ norm,
                            const int*   __restrict__ dst,
                            const float* __restrict__ r) {
    int i = blockIdx.x * blockDim.x + threadIdx.x;
    if (i >= PREP_T) return;
    atomicAdd(&g_cnt[__ldg(dst + i)], 1);    // PREP_T == N_EDGES

    if (i < N_RELS * D4) {
        float4 rv = __ldg(reinterpret_cast<const float4*>(r) + i);
        uint2 u;
        u.x = pack_h2(rv.x, rv.y);
        u.y = pack_h2(rv.z, rv.w);
        reinterpret_cast<uint2*>(g_rh)[i] = u;
    }

    const float4* h4 = reinterpret_cast<const float4*>(h);
    float4* o4 = reinterpret_cast<float4*>(g_hn);
    uint2*  o2 = reinterpret_cast<uint2*>(g_hnh);
    int j0 = i, j1 = i + PREP_T;
    float4 v0 = h4[j0];
    float4 v1 = h4[j1];
    float n0 = __ldg(norm + j0 / D4);
    float n1 = __ldg(norm + j1 / D4);
    v0.x *= n0; v0.y *= n0; v0.z *= n0; v0.w *= n0;
    v1.x *= n1; v1.y *= n1; v1.z *= n1; v1.w *= n1;
    o4[j0] = v0;
    o4[j1] = v1;
    uint2 u0, u1;
    u0.x = pack_h2(v0.x, v0.y); u0.y = pack_h2(v0.z, v0.w);
    u1.x = pack_h2(v1.x, v1.y); u1.y = pack_h2(v1.z, v1.w);
    o2[j0] = u0;
    o2[j1] = u1;
}

// ---------------------------------------------------------------------------
// Kernel 2a: per-chunk scan (coalesced). Resets g_cnt.
// ---------------------------------------------------------------------------
__global__ __launch_bounds__(SCAN_T, 1)
void k_scan1() {
    __shared__ int s[SCAN_T];
    int tid = threadIdx.x;
    int idx = blockIdx.x * SCAN_T + tid;
    int v = (idx < N_NODES) ? g_cnt[idx] : 0;
    if (idx < N_NODES) g_cnt[idx] = 0;
    s[tid] = v;
    __syncthreads();
    #pragma unroll
    for (int ofs = 1; ofs < SCAN_T; ofs <<= 1) {
        int t = (tid >= ofs) ? s[tid - ofs] : 0;
        __syncthreads();
        s[tid] += t;
        __syncthreads();
    }
    if (idx < N_NODES) g_off[idx] = s[tid] - v;
    if (tid == SCAN_T - 1) g_bsum[blockIdx.x] = s[tid];
}

// ---------------------------------------------------------------------------
// Kernel 2b: add chunk prefix, write offsets + cursors.
// ---------------------------------------------------------------------------
__global__ __launch_bounds__(SCAN_T, 1)
void k_scan2() {
    __shared__ int sb[64];
    int tid = threadIdx.x;
    if (tid < N_CHUNKS) sb[tid] = g_bsum[tid];
    __syncthreads();
    int prefix = 0;
    for (int i = 0; i < blockIdx.x; i++) prefix += sb[i];
    int idx = blockIdx.x * SCAN_T + tid;
    if (idx < N_NODES) {
        int o = g_off[idx] + prefix;
        g_off[idx] = o;
        g_cur[idx] = o;
    }
    if (idx == 0) g_off[N_NODES] = N_EDGES;
}

// ---------------------------------------------------------------------------
// Kernel 3: CSR fill — 2 edges per thread (best measured config).
// ---------------------------------------------------------------------------
__global__ void k_fill(const int* __restrict__ src,
                       const int* __restrict__ dst,
                       const int* __restrict__ rel) {
    int t = blockIdx.x * blockDim.x + threadIdx.x;
    int e0 = t * 2, e1 = t * 2 + 1;
    if (e0 >= N_EDGES) return;
    int d0 = __ldg(dst + e0);
    int k0 = (__ldg(src + e0) << 8) | __ldg(rel + e0);
    int d1 = __ldg(dst + e1);
    int k1 = (__ldg(src + e1) << 8) | __ldg(rel + e1);
    int p0 = atomicAdd(&g_cur[d0], 1);
    int p1 = atomicAdd(&g_cur[d1], 1);
    g_ekey[p0] = k0;
    g_ekey[p1] = k1;
}

// ---------------------------------------------------------------------------
// Kernel 4: gather — one warp per dst node, fp16 operands, fp32 accumulation.
// Latency-chain fix: keys prefetched COALESCED (lane l reads key e0+l, one
// 128B request per 32 edges), broadcast via shfl; hn loads issued 8-deep.
// ---------------------------------------------------------------------------
__device__ __forceinline__ void acc_edge(float4& acc, uint2 u, uint2 w) {
    __half2 d0 = __hsub2(*reinterpret_cast<__half2*>(&u.x),
                         *reinterpret_cast<__half2*>(&w.x));
    __half2 d1 = __hsub2(*reinterpret_cast<__half2*>(&u.y),
                         *reinterpret_cast<__half2*>(&w.y));
    float2 f0 = __half22float2(d0);
    float2 f1 = __half22float2(d1);
    acc.x += f0.x; acc.y += f0.y; acc.z += f1.x; acc.w += f1.y;
}

__global__ void k_gather(const float* __restrict__ norm) {
    int warp = (blockIdx.x * blockDim.x + threadIdx.x) >> 5;
    int lane = threadIdx.x & 31;
    if (warp >= N_NODES) return;

    int e0 = __ldg(g_off + warp);
    int e1 = __ldg(g_off + warp + 1);

    const uint2* hh = reinterpret_cast<const uint2*>(g_hnh);  // row stride 32
    const uint2* rr = reinterpret_cast<const uint2*>(g_rh);

    float4 acc0 = make_float4(0.f, 0.f, 0.f, 0.f);
    float4 acc1 = make_float4(0.f, 0.f, 0.f, 0.f);

    for (int base = e0; base < e1; base += 32) {
        int n = min(32, e1 - base);
        int key = 0;
        if (base + lane < e1) key = __ldg(g_ekey + base + lane);   // coalesced

        int j = 0;
        for (; j + 8 <= n; j += 8) {
            uint2 u[8], w[8];
            #pragma unroll
            for (int t = 0; t < 8; t++) {
                int k = __shfl_sync(0xffffffffu, key, j + t);
                u[t] = __ldcg(hh + (k >> 8) * 32 + lane);
                w[t] = __ldg(rr + (k & 255) * 32 + lane);
            }
            #pragma unroll
            for (int t = 0; t < 8; t++) {
                if (t & 1) acc_edge(acc1, u[t], w[t]);
                else       acc_edge(acc0, u[t], w[t]);
            }
        }
        // remainder (<8), still latency-overlapped in pairs
        for (; j + 2 <= n; j += 2) {
            int ka = __shfl_sync(0xffffffffu, key, j);
            int kb = __shfl_sync(0xffffffffu, key, j + 1);
            uint2 ua = __ldcg(hh + (ka >> 8) * 32 + lane);
            uint2 ub = __ldcg(hh + (kb >> 8) * 32 + lane);
            uint2 wa = __ldg(rr + (ka & 255) * 32 + lane);
            uint2 wb = __ldg(rr + (kb & 255) * 32 + lane);
            acc_edge(acc0, ua, wa);
            acc_edge(acc1, ub, wb);
        }
        if (j < n) {
            int k = __shfl_sync(0xffffffffu, key, j);
            uint2 u = __ldcg(hh + (k >> 8) * 32 + lane);
            uint2 w = __ldg(rr + (k & 255) * 32 + lane);
            acc_edge(acc0, u, w);
        }
    }

    float nm = __ldg(norm + warp);
    float4 o;
    o.x = (acc0.x + acc1.x) * nm;
    o.y = (acc0.y + acc1.y) * nm;
    o.z = (acc0.z + acc1.z) * nm;
    o.w = (acc0.w + acc1.w) * nm;
    reinterpret_cast<float4*>(g_agg)[warp * D4 + lane] = o;
}

// ---------------------------------------------------------------------------
// Kernel 5: tf32 mma.sync GEMM  out = relu( [hn | agg] @ [W ; W_msg] + b )
// Block tile 128x128, 8 warps; warp = 32 rows x 64 cols (2 m16 x 8 n8, k8).
// ---------------------------------------------------------------------------
#define LDB 136
#define LDA 36
#define SB_WORDS (256 * LDB)
#define SA_WORDS (128 * LDA)
#define SMEM_TC  ((SB_WORDS + 2 * SA_WORDS) * 4)   // 176,128 bytes

__global__ __launch_bounds__(256, 1)
void k_gemm_tc(const float* __restrict__ W,
               const float* __restrict__ W_msg,
               const float* __restrict__ bias,
               float* __restrict__ out) {
    extern __shared__ uint32_t smw[];
    uint32_t* sB = smw;                 // [256][LDB]
    uint32_t* sA = smw + SB_WORDS;      // 2 x [128][LDA]

    const int tid = threadIdx.x;
    const int wid = tid >> 5;
    const int lane = tid & 31;
    const int g  = lane >> 2;
    const int tg = lane & 3;
    const int tileBase = blockIdx.x * 128;
    const int wrb = (wid & 3) * 32;
    const int wcb = (wid >> 2) * 64;

    {
        #pragma unroll
        for (int i = tid; i < 256 * 32; i += 256) {
            int k = i >> 5, f4 = i & 31;
            const float4* srcp = (k < 128)
                ? reinterpret_cast<const float4*>(W) + k * 32 + f4
                : reinterpret_cast<const float4*>(W_msg) + (k - 128) * 32 + f4;
            float4 v = __ldg(srcp);
            uint4 t;
            t.x = f2tf32(v.x); t.y = f2tf32(v.y);
            t.z = f2tf32(v.z); t.w = f2tf32(v.w);
            *reinterpret_cast<uint4*>(sB + k * LDB + f4 * 4) = t;
        }
    }

    auto loadA = [&](int c, uint32_t* buf) {
        const float4* src = reinterpret_cast<const float4*>((c < 4) ? g_hn : g_agg);
        int kc = (c & 3) * 8;
        #pragma unroll
        for (int i = tid; i < 128 * 8; i += 256) {
            int row = i >> 3, f4 = i & 7;
            int gr = tileBase + row;
            float4 v = make_float4(0.f, 0.f, 0.f, 0.f);
            if (gr < N_NODES) v = __ldcg(src + gr * 32 + kc + f4);
            uint4 t;
            t.x = f2tf32(v.x); t.y = f2tf32(v.y);
            t.z = f2tf32(v.z); t.w = f2tf32(v.w);
            *reinterpret_cast<uint4*>(buf + row * LDA + f4 * 4) = t;
        }
    };

    float acc[2][8][4];
    #pragma unroll
    for (int mt = 0; mt < 2; mt++)
        #pragma unroll
        for (int nt = 0; nt < 8; nt++)
            #pragma unroll
            for (int cc = 0; cc < 4; cc++) acc[mt][nt][cc] = 0.f;

    loadA(0, sA);
    __syncthreads();

    #pragma unroll
    for (int c = 0; c < 8; c++) {
        if (c + 1 < 8) loadA(c + 1, sA + ((c + 1) & 1) * SA_WORDS);
        const uint32_t* A = sA + (c & 1) * SA_WORDS;
        const uint32_t* Bc = sB + c * 32 * LDB;

        #pragma unroll
        for (int ks = 0; ks < 4; ks++) {
            int k0 = ks * 8;
            uint32_t afr[2][4];
            #pragma unroll
            for (int mt = 0; mt < 2; mt++) {
                int rb = wrb + mt * 16 + g;
                afr[mt][0] = A[rb * LDA + k0 + tg];
                afr[mt][1] = A[(rb + 8) * LDA + k0 + tg];
                afr[mt][2] = A[rb * LDA + k0 + tg + 4];
                afr[mt][3] = A[(rb + 8) * LDA + k0 + tg + 4];
            }
            #pragma unroll
            for (int nt = 0; nt < 8; nt++) {
                uint32_t bfr[2];
                int ncol = wcb + nt * 8 + g;
                bfr[0] = Bc[(k0 + tg) * LDB + ncol];
                bfr[1] = Bc[(k0 + tg + 4) * LDB + ncol];
                mma_tf32(acc[0][nt], afr[0], bfr);
                mma_tf32(acc[1][nt], afr[1], bfr);
            }
        }
        __syncthreads();
    }

    #pragma unroll
    for (int mt = 0; mt < 2; mt++) {
        int r0 = tileBase + wrb + mt * 16 + g;
        int r1 = r0 + 8;
        #pragma unroll
        for (int nt = 0; nt < 8; nt++) {
            int col = wcb + nt * 8 + tg * 2;
            float2 bb = *reinterpret_cast<const float2*>(bias + col);
            if (r0 < N_NODES) {
                float2 o;
                o.x = fmaxf(acc[mt][nt][0] + bb.x, 0.f);
                o.y = fmaxf(acc[mt][nt][1] + bb.y, 0.f);
                *reinterpret_cast<float2*>(out + r0 * D + col) = o;
            }
            if (r1 < N_NODES) {
                float2 o;
                o.x = fmaxf(acc[mt][nt][2] + bb.x, 0.f);
                o.y = fmaxf(acc[mt][nt][3] + bb.y, 0.f);
                *reinterpret_cast<float2*>(out + r1 * D + col) = o;
            }
        }
    }
}

// ---------------------------------------------------------------------------
extern "C" void kernel_launch(void* const* d_in, const int* in_sizes, int n_in,
                              void* d_out, int out_size) {
    const float* h     = (const float*)d_in[0];
    const float* r     = (const float*)d_in[1];
    const float* norm  = (const float*)d_in[2];
    const int*   src   = (const int*)d_in[3];
    const int*   dst   = (const int*)d_in[4];
    const int*   rel   = (const int*)d_in[5];
    const float* W_msg = (const float*)d_in[6];
    const float* W     = (const float*)d_in[7];
    const float* b     = (const float*)d_in[8];
    float* out = (float*)d_out;

    // fused prep: hn (fp32 + fp16 mirror), r fp16 mirror, dst histogram
    k_prep_hist<<<(PREP_T + 255) / 256, 256>>>(h, norm, dst, r);

    // coalesced two-phase scan
    k_scan1<<<N_CHUNKS, SCAN_T>>>();
    k_scan2<<<N_CHUNKS, SCAN_T>>>();

    // CSR fill (2 edges/thread)
    k_fill<<<(N_EDGES / 2 + 255) / 256, 256>>>(src, dst, rel);

    // gather (one warp per node, coalesced key prefetch + shfl broadcast)
    k_gather<<<(N_NODES * 32 + 255) / 256, 256>>>(norm);

    // tf32 mma.sync GEMM + epilogue
    cudaFuncSetAttribute(k_gemm_tc, cudaFuncAttributeMaxDynamicSharedMemorySize, SMEM_TC);
    k_gemm_tc<<<(N_NODES + 127) / 128, 256, SMEM_TC>>>(W, W_msg, b, out);
}

// round 13
// speedup vs baseline: 1.1066x; 1.1066x over previous
#include <cuda_runtime.h>
#include <cuda_fp16.h>
#include <cstdint>

#define N_NODES 50000
#define N_EDGES 800000
#define N_RELS  200
#define D       128
#define D4      (D/4)

#define SCAN_T   1024
#define N_CHUNKS ((N_NODES + SCAN_T - 1) / SCAN_T)   // 49

// Scratch (allocation-free rule: __device__ globals)
__device__ __half    g_hnh[N_NODES * D];   // fp16 h*norm (gather operand)
__device__ __half    g_rh[N_RELS * D];     // fp16 mirror of r
__device__ float     g_agg[N_NODES * D];   // norm * segment_sum(hn[src]-r[rel], dst)
__device__ int       g_cnt[N_NODES];       // per-dst degree (zero at entry; k_scan resets)
__device__ int       g_off[N_NODES + 1];   // CSR offsets
__device__ int       g_cur[N_NODES];       // running fill cursors
__device__ int       g_ekey[N_EDGES];      // packed (src<<8)|rel, bucketed by dst
__device__ unsigned  g_desc[64];           // block aggregates (bit31=valid); prep resets

// ---------------------------------------------------------------------------
// tf32 helpers (baseline PTX, no 'a' features)
// ---------------------------------------------------------------------------
__device__ __forceinline__ uint32_t f2tf32(float f) {
    uint32_t t;
    asm("cvt.rna.tf32.f32 %0, %1;" : "=r"(t) : "f"(f));
    return t;
}
__device__ __forceinline__ void mma_tf32(float* c, const uint32_t* a, const uint32_t* b) {
    asm volatile(
        "mma.sync.aligned.m16n8k8.row.col.f32.tf32.tf32.f32 "
        "{%0,%1,%2,%3}, {%4,%5,%6,%7}, {%8,%9}, {%0,%1,%2,%3};"
        : "+f"(c[0]), "+f"(c[1]), "+f"(c[2]), "+f"(c[3])
        : "r"(a[0]), "r"(a[1]), "r"(a[2]), "r"(a[3]), "r"(b[0]), "r"(b[1]));
}
__device__ __forceinline__ uint32_t pack_h2(float a, float b) {
    __half2 h = __floats2half2_rn(a, b);
    return *reinterpret_cast<uint32_t*>(&h);
}

// ---------------------------------------------------------------------------
// Kernel 1 (fused): hnh = fp16(h * norm); r -> fp16; dst histogram; desc reset.
// g_cnt zero at entry (static init; k_scan restores each run).
// ---------------------------------------------------------------------------
#define PREP_T (N_NODES * D4 / 2)   // 800,000 threads == N_EDGES

__global__ void k_prep_hist(const float* __restrict__ h,
                            const float* __restrict__ norm,
                            const int*   __restrict__ dst,
                            const float* __restrict__ r) {
    int i = blockIdx.x * blockDim.x + threadIdx.x;
    if (i >= PREP_T) return;
    if (i < 64) g_desc[i] = 0;               // reset scan descriptors
    atomicAdd(&g_cnt[__ldg(dst + i)], 1);    // PREP_T == N_EDGES

    if (i < N_RELS * D4) {
        float4 rv = __ldg(reinterpret_cast<const float4*>(r) + i);
        uint2 u;
        u.x = pack_h2(rv.x, rv.y);
        u.y = pack_h2(rv.z, rv.w);
        reinterpret_cast<uint2*>(g_rh)[i] = u;
    }

    const float4* h4 = reinterpret_cast<const float4*>(h);
    uint2* o2 = reinterpret_cast<uint2*>(g_hnh);
    int j0 = i, j1 = i + PREP_T;
    float4 v0 = h4[j0];
    float4 v1 = h4[j1];
    float n0 = __ldg(norm + j0 / D4);
    float n1 = __ldg(norm + j1 / D4);
    uint2 u0, u1;
    u0.x = pack_h2(v0.x * n0, v0.y * n0);
    u0.y = pack_h2(v0.z * n0, v0.w * n0);
    u1.x = pack_h2(v1.x * n1, v1.y * n1);
    u1.y = pack_h2(v1.z * n1, v1.w * n1);
    o2[j0] = u0;
    o2[j1] = u1;
}

// ---------------------------------------------------------------------------
// Kernel 2: single-pass scan, 49 blocks (all co-resident -> polling is safe).
// Coalesced loads, block Hillis-Steele, decoupled aggregate lookback.
// Resets g_cnt. Writes g_off + g_cur + sentinel.
// ---------------------------------------------------------------------------
__global__ __launch_bounds__(SCAN_T, 1)
void k_scan() {
    __shared__ int s[SCAN_T];
    __shared__ int s2[64];
    __shared__ int s_prefix;
    const int tid = threadIdx.x;
    const int b = blockIdx.x;
    const int idx = b * SCAN_T + tid;

    int v = (idx < N_NODES) ? g_cnt[idx] : 0;
    if (idx < N_NODES) g_cnt[idx] = 0;       // restore invariant (coalesced)
    s[tid] = v;
    __syncthreads();
    #pragma unroll
    for (int ofs = 1; ofs < SCAN_T; ofs <<= 1) {
        int t = (tid >= ofs) ? s[tid - ofs] : 0;
        __syncthreads();
        s[tid] += t;
        __syncthreads();
    }

    // publish this block's aggregate (payload rides in the atomic word itself)
    if (tid == SCAN_T - 1)
        *reinterpret_cast<volatile unsigned*>(&g_desc[b]) = 0x80000000u | (unsigned)s[tid];

    // parallel lookback: thread j < b polls predecessor j's aggregate
    if (tid < b) {
        unsigned u;
        do {
            u = *reinterpret_cast<volatile unsigned*>(&g_desc[tid]);
        } while (!(u & 0x80000000u));
        s2[tid] = (int)(u & 0x7FFFFFFFu);
    }
    __syncthreads();
    if (tid == 0) {
        int p = 0;
        for (int j = 0; j < b; j++) p += s2[j];
        s_prefix = p;
    }
    __syncthreads();

    if (idx < N_NODES) {
        int o = s_prefix + s[tid] - v;       // exclusive global prefix
        g_off[idx] = o;
        g_cur[idx] = o;
    }
    if (b == 0 && tid == 0) g_off[N_NODES] = N_EDGES;
}

// ---------------------------------------------------------------------------
// Kernel 3: CSR fill — 2 edges per thread (best measured config).
// ---------------------------------------------------------------------------
__global__ void k_fill(const int* __restrict__ src,
                       const int* __restrict__ dst,
                       const int* __restrict__ rel) {
    int t = blockIdx.x * blockDim.x + threadIdx.x;
    int e0 = t * 2, e1 = t * 2 + 1;
    if (e0 >= N_EDGES) return;
    int d0 = __ldg(dst + e0);
    int k0 = (__ldg(src + e0) << 8) | __ldg(rel + e0);
    int d1 = __ldg(dst + e1);
    int k1 = (__ldg(src + e1) << 8) | __ldg(rel + e1);
    int p0 = atomicAdd(&g_cur[d0], 1);
    int p1 = atomicAdd(&g_cur[d1], 1);
    g_ekey[p0] = k0;
    g_ekey[p1] = k1;
}

// ---------------------------------------------------------------------------
// Kernel 4: gather — FROZEN from round 9/12 (clean profiling target).
// One warp per dst node; coalesced key prefetch + shfl broadcast; fp16 loads.
// ---------------------------------------------------------------------------
__device__ __forceinline__ void acc_edge(float4& acc, uint2 u, uint2 w) {
    __half2 d0 = __hsub2(*reinterpret_cast<__half2*>(&u.x),
                         *reinterpret_cast<__half2*>(&w.x));
    __half2 d1 = __hsub2(*reinterpret_cast<__half2*>(&u.y),
                         *reinterpret_cast<__half2*>(&w.y));
    float2 f0 = __half22float2(d0);
    float2 f1 = __half22float2(d1);
    acc.x += f0.x; acc.y += f0.y; acc.z += f1.x; acc.w += f1.y;
}

__global__ void k_gather(const float* __restrict__ norm) {
    int warp = (blockIdx.x * blockDim.x + threadIdx.x) >> 5;
    int lane = threadIdx.x & 31;
    if (warp >= N_NODES) return;

    int e0 = __ldg(g_off + warp);
    int e1 = __ldg(g_off + warp + 1);

    const uint2* hh = reinterpret_cast<const uint2*>(g_hnh);
    const uint2* rr = reinterpret_cast<const uint2*>(g_rh);

    float4 acc0 = make_float4(0.f, 0.f, 0.f, 0.f);
    float4 acc1 = make_float4(0.f, 0.f, 0.f, 0.f);

    for (int base = e0; base < e1; base += 32) {
        int n = min(32, e1 - base);
        int key = 0;
        if (base + lane < e1) key = __ldg(g_ekey + base + lane);

        int j = 0;
        for (; j + 8 <= n; j += 8) {
            uint2 u[8], w[8];
            #pragma unroll
            for (int t = 0; t < 8; t++) {
                int k = __shfl_sync(0xffffffffu, key, j + t);
                u[t] = __ldcg(hh + (k >> 8) * 32 + lane);
                w[t] = __ldg(rr + (k & 255) * 32 + lane);
            }
            #pragma unroll
            for (int t = 0; t < 8; t++) {
                if (t & 1) acc_edge(acc1, u[t], w[t]);
                else       acc_edge(acc0, u[t], w[t]);
            }
        }
        for (; j + 2 <= n; j += 2) {
            int ka = __shfl_sync(0xffffffffu, key, j);
            int kb = __shfl_sync(0xffffffffu, key, j + 1);
            uint2 ua = __ldcg(hh + (ka >> 8) * 32 + lane);
            uint2 ub = __ldcg(hh + (kb >> 8) * 32 + lane);
            uint2 wa = __ldg(rr + (ka & 255) * 32 + lane);
            uint2 wb = __ldg(rr + (kb & 255) * 32 + lane);
            acc_edge(acc0, ua, wa);
            acc_edge(acc1, ub, wb);
        }
        if (j < n) {
            int k = __shfl_sync(0xffffffffu, key, j);
            uint2 u = __ldcg(hh + (k >> 8) * 32 + lane);
            uint2 w = __ldg(rr + (k & 255) * 32 + lane);
            acc_edge(acc0, u, w);
        }
    }

    float nm = __ldg(norm + warp);
    float4 o;
    o.x = (acc0.x + acc1.x) * nm;
    o.y = (acc0.y + acc1.y) * nm;
    o.z = (acc0.z + acc1.z) * nm;
    o.w = (acc0.w + acc1.w) * nm;
    reinterpret_cast<float4*>(g_agg)[warp * D4 + lane] = o;
}

// ---------------------------------------------------------------------------
// Kernel 5: tf32 mma.sync GEMM  out = relu( [h*norm | agg] @ [W ; W_msg] + b )
// A chunks c<4 read h directly and apply norm on the fly (g_hn eliminated).
// ---------------------------------------------------------------------------
#define LDB 136
#define LDA 36
#define SB_WORDS (256 * LDB)
#define SA_WORDS (128 * LDA)
#define SMEM_TC  ((SB_WORDS + 2 * SA_WORDS) * 4)   // 176,128 bytes

__global__ __launch_bounds__(256, 1)
void k_gemm_tc(const float* __restrict__ h,
               const float* __restrict__ norm,
               const float* __restrict__ W,
               const float* __restrict__ W_msg,
               const float* __restrict__ bias,
               float* __restrict__ out) {
    extern __shared__ uint32_t smw[];
    uint32_t* sB = smw;                 // [256][LDB]
    uint32_t* sA = smw + SB_WORDS;      // 2 x [128][LDA]

    const int tid = threadIdx.x;
    const int wid = tid >> 5;
    const int lane = tid & 31;
    const int g  = lane >> 2;
    const int tg = lane & 3;
    const int tileBase = blockIdx.x * 128;
    const int wrb = (wid & 3) * 32;
    const int wcb = (wid >> 2) * 64;

    {
        #pragma unroll
        for (int i = tid; i < 256 * 32; i += 256) {
            int k = i >> 5, f4 = i & 31;
            const float4* srcp = (k < 128)
                ? reinterpret_cast<const float4*>(W) + k * 32 + f4
                : reinterpret_cast<const float4*>(W_msg) + (k - 128) * 32 + f4;
            float4 v = __ldg(srcp);
            uint4 t;
            t.x = f2tf32(v.x); t.y = f2tf32(v.y);
            t.z = f2tf32(v.z); t.w = f2tf32(v.w);
            *reinterpret_cast<uint4*>(sB + k * LDB + f4 * 4) = t;
        }
    }

    auto loadA = [&](int c, uint32_t* buf) {
        int kc = (c & 3) * 8;
        #pragma unroll
        for (int i = tid; i < 128 * 8; i += 256) {
            int row = i >> 3, f4 = i & 7;
            int gr = tileBase + row;
            float4 v = make_float4(0.f, 0.f, 0.f, 0.f);
            if (gr < N_NODES) {
                if (c < 4) {
                    v = __ldg(reinterpret_cast<const float4*>(h) + gr * 32 + kc + f4);
                    float nm = __ldg(norm + gr);
                    v.x *= nm; v.y *= nm; v.z *= nm; v.w *= nm;
                } else {
                    v = __ldcg(reinterpret_cast<const float4*>(g_agg) + gr * 32 + kc + f4);
                }
            }
            uint4 t;
            t.x = f2tf32(v.x); t.y = f2tf32(v.y);
            t.z = f2tf32(v.z); t.w = f2tf32(v.w);
            *reinterpret_cast<uint4*>(buf + row * LDA + f4 * 4) = t;
        }
    };

    float acc[2][8][4];
    #pragma unroll
    for (int mt = 0; mt < 2; mt++)
        #pragma unroll
        for (int nt = 0; nt < 8; nt++)
            #pragma unroll
            for (int cc = 0; cc < 4; cc++) acc[mt][nt][cc] = 0.f;

    loadA(0, sA);
    __syncthreads();

    #pragma unroll
    for (int c = 0; c < 8; c++) {
        if (c + 1 < 8) loadA(c + 1, sA + ((c + 1) & 1) * SA_WORDS);
        const uint32_t* A = sA + (c & 1) * SA_WORDS;
        const uint32_t* Bc = sB + c * 32 * LDB;

        #pragma unroll
        for (int ks = 0; ks < 4; ks++) {
            int k0 = ks * 8;
            uint32_t afr[2][4];
            #pragma unroll
            for (int mt = 0; mt < 2; mt++) {
                int rb = wrb + mt * 16 + g;
                afr[mt][0] = A[rb * LDA + k0 + tg];
                afr[mt][1] = A[(rb + 8) * LDA + k0 + tg];
                afr[mt][2] = A[rb * LDA + k0 + tg + 4];
                afr[mt][3] = A[(rb + 8) * LDA + k0 + tg + 4];
            }
            #pragma unroll
            for (int nt = 0; nt < 8; nt++) {
                uint32_t bfr[2];
                int ncol = wcb + nt * 8 + g;
                bfr[0] = Bc[(k0 + tg) * LDB + ncol];
                bfr[1] = Bc[(k0 + tg + 4) * LDB + ncol];
                mma_tf32(acc[0][nt], afr[0], bfr);
                mma_tf32(acc[1][nt], afr[1], bfr);
            }
        }
        __syncthreads();
    }

    #pragma unroll
    for (int mt = 0; mt < 2; mt++) {
        int r0 = tileBase + wrb + mt * 16 + g;
        int r1 = r0 + 8;
        #pragma unroll
        for (int nt = 0; nt < 8; nt++) {
            int col = wcb + nt * 8 + tg * 2;
            float2 bb = *reinterpret_cast<const float2*>(bias + col);
            if (r0 < N_NODES) {
                float2 o;
                o.x = fmaxf(acc[mt][nt][0] + bb.x, 0.f);
                o.y = fmaxf(acc[mt][nt][1] + bb.y, 0.f);
                *reinterpret_cast<float2*>(out + r0 * D + col) = o;
            }
            if (r1 < N_NODES) {
                float2 o;
                o.x = fmaxf(acc[mt][nt][2] + bb.x, 0.f);
                o.y = fmaxf(acc[mt][nt][3] + bb.y, 0.f);
                *reinterpret_cast<float2*>(out + r1 * D + col) = o;
            }
        }
    }
}

// ---------------------------------------------------------------------------
extern "C" void kernel_launch(void* const* d_in, const int* in_sizes, int n_in,
                              void* d_out, int out_size) {
    const float* h     = (const float*)d_in[0];
    const float* r     = (const float*)d_in[1];
    const float* norm  = (const float*)d_in[2];
    const int*   src   = (const int*)d_in[3];
    const int*   dst   = (const int*)d_in[4];
    const int*   rel   = (const int*)d_in[5];
    const float* W_msg = (const float*)d_in[6];
    const float* W     = (const float*)d_in[7];
    const float* b     = (const float*)d_in[8];
    float* out = (float*)d_out;

    // fused prep: fp16 hn mirror, r mirror, dst histogram, desc reset
    k_prep_hist<<<(PREP_T + 255) / 256, 256>>>(h, norm, dst, r);

    // single-pass scan (decoupled block aggregates)
    k_scan<<<N_CHUNKS, SCAN_T>>>();

    // CSR fill (2 edges/thread)
    k_fill<<<(N_EDGES / 2 + 255) / 256, 256>>>(src, dst, rel);

    // gather (frozen config — intended ncu capture target this round)
    k_gather<<<(N_NODES * 32 + 255) / 256, 256>>>(norm);

    // tf32 mma.sync GEMM + epilogue (h*norm applied on the fly)
    cudaFuncSetAttribute(k_gemm_tc, cudaFuncAttributeMaxDynamicSharedMemorySize, SMEM_TC);
    k_gemm_tc<<<(N_NODES + 127) / 128, 256, SMEM_TC>>>(h, norm, W, W_msg, b, out);
}

// round 14
// speedup vs baseline: 1.1226x; 1.0145x over previous
#include <cuda_runtime.h>
#include <cuda_fp16.h>
#include <cstdint>

#define N_NODES 50000
#define N_EDGES 800000
#define N_RELS  200
#define D       128
#define D4      (D/4)

#define SCAN_T   1024
#define N_CHUNKS ((N_NODES + SCAN_T - 1) / SCAN_T)   // 49

// Scratch (allocation-free rule: __device__ globals)
__device__ __half    g_hnh[N_NODES * D];   // fp16 h*norm (gather operand)
__device__ __half    g_rh[N_RELS * D];     // fp16 mirror of r
__device__ float     g_agg[N_NODES * D];   // norm * segment_sum(hn[src]-r[rel], dst)
__device__ int       g_cnt[N_NODES];       // per-dst degree (zero at entry; k_scan resets)
__device__ int       g_off[N_NODES + 1];   // CSR offsets
__device__ int       g_rank[N_EDGES];      // edge rank within its dst bucket (from prep)
__device__ int       g_ekey[N_EDGES];      // packed (src<<8)|rel, bucketed by dst
__device__ unsigned  g_desc[64];           // block aggregates (bit31=valid); prep resets

// ---------------------------------------------------------------------------
// tf32 helpers (baseline PTX, no 'a' features)
// ---------------------------------------------------------------------------
__device__ __forceinline__ uint32_t f2tf32(float f) {
    uint32_t t;
    asm("cvt.rna.tf32.f32 %0, %1;" : "=r"(t) : "f"(f));
    return t;
}
__device__ __forceinline__ void mma_tf32(float* c, const uint32_t* a, const uint32_t* b) {
    asm volatile(
        "mma.sync.aligned.m16n8k8.row.col.f32.tf32.tf32.f32 "
        "{%0,%1,%2,%3}, {%4,%5,%6,%7}, {%8,%9}, {%0,%1,%2,%3};"
        : "+f"(c[0]), "+f"(c[1]), "+f"(c[2]), "+f"(c[3])
        : "r"(a[0]), "r"(a[1]), "r"(a[2]), "r"(a[3]), "r"(b[0]), "r"(b[1]));
}
__device__ __forceinline__ uint32_t pack_h2(float a, float b) {
    __half2 h = __floats2half2_rn(a, b);
    return *reinterpret_cast<uint32_t*>(&h);
}

// ---------------------------------------------------------------------------
// Kernel 1 (fused): hnh = fp16(h*norm); r -> fp16; dst histogram + edge RANK.
// g_cnt zero at entry (static init; k_scan restores each run).
// ---------------------------------------------------------------------------
#define PREP_T (N_NODES * D4 / 2)   // 800,000 threads == N_EDGES

__global__ void k_prep_hist(const float* __restrict__ h,
                            const float* __restrict__ norm,
                            const int*   __restrict__ dst,
                            const float* __restrict__ r) {
    int i = blockIdx.x * blockDim.x + threadIdx.x;
    if (i >= PREP_T) return;
    if (i < 64) g_desc[i] = 0;                       // reset scan descriptors
    g_rank[i] = atomicAdd(&g_cnt[__ldg(dst + i)], 1); // rank within dst bucket

    if (i < N_RELS * D4) {
        float4 rv = __ldg(reinterpret_cast<const float4*>(r) + i);
        uint2 u;
        u.x = pack_h2(rv.x, rv.y);
        u.y = pack_h2(rv.z, rv.w);
        reinterpret_cast<uint2*>(g_rh)[i] = u;
    }

    const float4* h4 = reinterpret_cast<const float4*>(h);
    uint2* o2 = reinterpret_cast<uint2*>(g_hnh);
    int j0 = i, j1 = i + PREP_T;
    float4 v0 = h4[j0];
    float4 v1 = h4[j1];
    float n0 = __ldg(norm + j0 / D4);
    float n1 = __ldg(norm + j1 / D4);
    uint2 u0, u1;
    u0.x = pack_h2(v0.x * n0, v0.y * n0);
    u0.y = pack_h2(v0.z * n0, v0.w * n0);
    u1.x = pack_h2(v1.x * n1, v1.y * n1);
    u1.y = pack_h2(v1.z * n1, v1.w * n1);
    o2[j0] = u0;
    o2[j1] = u1;
}

// ---------------------------------------------------------------------------
// Kernel 2: single-pass scan, 49 co-resident blocks, decoupled lookback.
// Resets g_cnt. Writes g_off + sentinel.
// ---------------------------------------------------------------------------
__global__ __launch_bounds__(SCAN_T, 1)
void k_scan() {
    __shared__ int s[SCAN_T];
    __shared__ int s2[64];
    __shared__ int s_prefix;
    const int tid = threadIdx.x;
    const int b = blockIdx.x;
    const int idx = b * SCAN_T + tid;

    int v = (idx < N_NODES) ? g_cnt[idx] : 0;
    if (idx < N_NODES) g_cnt[idx] = 0;       // restore invariant (coalesced)
    s[tid] = v;
    __syncthreads();
    #pragma unroll
    for (int ofs = 1; ofs < SCAN_T; ofs <<= 1) {
        int t = (tid >= ofs) ? s[tid - ofs] : 0;
        __syncthreads();
        s[tid] += t;
        __syncthreads();
    }

    if (tid == SCAN_T - 1)
        *reinterpret_cast<volatile unsigned*>(&g_desc[b]) = 0x80000000u | (unsigned)s[tid];

    if (tid < b) {
        unsigned u;
        do {
            u = *reinterpret_cast<volatile unsigned*>(&g_desc[tid]);
        } while (!(u & 0x80000000u));
        s2[tid] = (int)(u & 0x7FFFFFFFu);
    }
    __syncthreads();
    if (tid == 0) {
        int p = 0;
        for (int j = 0; j < b; j++) p += s2[j];
        s_prefix = p;
    }
    __syncthreads();

    if (idx < N_NODES) g_off[idx] = s_prefix + s[tid] - v;   // exclusive prefix
    if (b == 0 && tid == 0) g_off[N_NODES] = N_EDGES;
}

// ---------------------------------------------------------------------------
// Kernel 3: CSR fill — NO ATOMICS: pos = g_off[dst] + rank (rank from prep).
// Pure streaming loads + one scattered STG per edge.
// ---------------------------------------------------------------------------
__global__ void k_fill(const int* __restrict__ src,
                       const int* __restrict__ dst,
                       const int* __restrict__ rel) {
    int t = blockIdx.x * blockDim.x + threadIdx.x;
    int e0 = t * 2, e1 = t * 2 + 1;
    if (e0 >= N_EDGES) return;
    int d0 = __ldg(dst + e0);
    int d1 = __ldg(dst + e1);
    int p0 = __ldg(g_off + d0) + __ldg(g_rank + e0);
    int p1 = __ldg(g_off + d1) + __ldg(g_rank + e1);
    g_ekey[p0] = (__ldg(src + e0) << 8) | __ldg(rel + e0);
    g_ekey[p1] = (__ldg(src + e1) << 8) | __ldg(rel + e1);
}

// ---------------------------------------------------------------------------
// Kernel 4: gather — HALF-WARP per edge (2 edges/warp-step), uint4 fp16 loads.
// 16 lanes x 16B = one 256B row. Issue count per edge ~halved vs full-warp.
// Keys prefetched coalesced (lane l reads key base+l), broadcast via shfl.
// ---------------------------------------------------------------------------
__device__ __forceinline__ void acc8(float* a, uint4 u, uint4 w) {
    __half2 d0 = __hsub2(*reinterpret_cast<__half2*>(&u.x),
                         *reinterpret_cast<__half2*>(&w.x));
    __half2 d1 = __hsub2(*reinterpret_cast<__half2*>(&u.y),
                         *reinterpret_cast<__half2*>(&w.y));
    __half2 d2 = __hsub2(*reinterpret_cast<__half2*>(&u.z),
                         *reinterpret_cast<__half2*>(&w.z));
    __half2 d3 = __hsub2(*reinterpret_cast<__half2*>(&u.w),
                         *reinterpret_cast<__half2*>(&w.w));
    float2 f0 = __half22float2(d0);
    float2 f1 = __half22float2(d1);
    float2 f2 = __half22float2(d2);
    float2 f3 = __half22float2(d3);
    a[0] += f0.x; a[1] += f0.y; a[2] += f1.x; a[3] += f1.y;
    a[4] += f2.x; a[5] += f2.y; a[6] += f3.x; a[7] += f3.y;
}

__global__ void k_gather(const float* __restrict__ norm) {
    int warp = (blockIdx.x * blockDim.x + threadIdx.x) >> 5;
    int lane = threadIdx.x & 31;
    if (warp >= N_NODES) return;
    const int hw  = lane >> 4;     // half-warp id (0/1)
    const int sub = lane & 15;     // lane within half-warp

    int e0 = __ldg(g_off + warp);
    int e1 = __ldg(g_off + warp + 1);

    const uint4* hh = reinterpret_cast<const uint4*>(g_hnh);  // row stride 16
    const uint4* rr = reinterpret_cast<const uint4*>(g_rh);

    float acc[8];
    #pragma unroll
    for (int i = 0; i < 8; i++) acc[i] = 0.f;

    for (int base = e0; base < e1; base += 32) {
        int n = min(32, e1 - base);
        int key = 0;
        if (base + lane < e1) key = __ldg(g_ekey + base + lane);   // coalesced

        int j = 0;
        // 8 edges per iteration (4 pairs), MLP=4 per lane
        for (; j + 8 <= n; j += 8) {
            uint4 u[4], w[4];
            #pragma unroll
            for (int t = 0; t < 4; t++) {
                int k = __shfl_sync(0xffffffffu, key, j + 2 * t + hw);
                u[t] = __ldcg(hh + (k >> 8) * 16 + sub);
                w[t] = __ldg(rr + (k & 255) * 16 + sub);
            }
            #pragma unroll
            for (int t = 0; t < 4; t++) acc8(acc, u[t], w[t]);
        }
        // pair remainder
        for (; j + 2 <= n; j += 2) {
            int k = __shfl_sync(0xffffffffu, key, j + hw);
            uint4 u = __ldcg(hh + (k >> 8) * 16 + sub);
            uint4 w = __ldg(rr + (k & 255) * 16 + sub);
            acc8(acc, u, w);
        }
        // odd single edge: first half-warp only
        if (j < n) {
            int k = __shfl_sync(0xffffffffu, key, j);
            if (hw == 0) {
                uint4 u = __ldcg(hh + (k >> 8) * 16 + sub);
                uint4 w = __ldg(rr + (k & 255) * 16 + sub);
                acc8(acc, u, w);
            }
        }
    }

    // combine the two half-warps (cols identical across halves)
    #pragma unroll
    for (int i = 0; i < 8; i++)
        acc[i] += __shfl_down_sync(0xffffffffu, acc[i], 16);

    if (hw == 0) {
        float nm = __ldg(norm + warp);
        float4 o0, o1;
        o0.x = acc[0] * nm; o0.y = acc[1] * nm;
        o0.z = acc[2] * nm; o0.w = acc[3] * nm;
        o1.x = acc[4] * nm; o1.y = acc[5] * nm;
        o1.z = acc[6] * nm; o1.w = acc[7] * nm;
        float4* op = reinterpret_cast<float4*>(g_agg) + warp * 32 + sub * 2;
        op[0] = o0;
        op[1] = o1;
    }
}

// ---------------------------------------------------------------------------
// Kernel 5: tf32 mma.sync GEMM  out = relu( [h*norm | agg] @ [W ; W_msg] + b )
// ---------------------------------------------------------------------------
#define LDB 136
#define LDA 36
#define SB_WORDS (256 * LDB)
#define SA_WORDS (128 * LDA)
#define SMEM_TC  ((SB_WORDS + 2 * SA_WORDS) * 4)   // 176,128 bytes

__global__ __launch_bounds__(256, 1)
void k_gemm_tc(const float* __restrict__ h,
               const float* __restrict__ norm,
               const float* __restrict__ W,
               const float* __restrict__ W_msg,
               const float* __restrict__ bias,
               float* __restrict__ out) {
    extern __shared__ uint32_t smw[];
    uint32_t* sB = smw;                 // [256][LDB]
    uint32_t* sA = smw + SB_WORDS;      // 2 x [128][LDA]

    const int tid = threadIdx.x;
    const int wid = tid >> 5;
    const int lane = tid & 31;
    const int g  = lane >> 2;
    const int tg = lane & 3;
    const int tileBase = blockIdx.x * 128;
    const int wrb = (wid & 3) * 32;
    const int wcb = (wid >> 2) * 64;

    {
        #pragma unroll
        for (int i = tid; i < 256 * 32; i += 256) {
            int k = i >> 5, f4 = i & 31;
            const float4* srcp = (k < 128)
                ? reinterpret_cast<const float4*>(W) + k * 32 + f4
                : reinterpret_cast<const float4*>(W_msg) + (k - 128) * 32 + f4;
            float4 v = __ldg(srcp);
            uint4 t;
            t.x = f2tf32(v.x); t.y = f2tf32(v.y);
            t.z = f2tf32(v.z); t.w = f2tf32(v.w);
            *reinterpret_cast<uint4*>(sB + k * LDB + f4 * 4) = t;
        }
    }

    auto loadA = [&](int c, uint32_t* buf) {
        int kc = (c & 3) * 8;
        #pragma unroll
        for (int i = tid; i < 128 * 8; i += 256) {
            int row = i >> 3, f4 = i & 7;
            int gr = tileBase + row;
            float4 v = make_float4(0.f, 0.f, 0.f, 0.f);
            if (gr < N_NODES) {
                if (c < 4) {
                    v = __ldg(reinterpret_cast<const float4*>(h) + gr * 32 + kc + f4);
                    float nm = __ldg(norm + gr);
                    v.x *= nm; v.y *= nm; v.z *= nm; v.w *= nm;
                } else {
                    v = __ldcg(reinterpret_cast<const float4*>(g_agg) + gr * 32 + kc + f4);
                }
            }
            uint4 t;
            t.x = f2tf32(v.x); t.y = f2tf32(v.y);
            t.z = f2tf32(v.z); t.w = f2tf32(v.w);
            *reinterpret_cast<uint4*>(buf + row * LDA + f4 * 4) = t;
        }
    };

    float acc[2][8][4];
    #pragma unroll
    for (int mt = 0; mt < 2; mt++)
        #pragma unroll
        for (int nt = 0; nt < 8; nt++)
            #pragma unroll
            for (int cc = 0; cc < 4; cc++) acc[mt][nt][cc] = 0.f;

    loadA(0, sA);
    __syncthreads();

    #pragma unroll
    for (int c = 0; c < 8; c++) {
        if (c + 1 < 8) loadA(c + 1, sA + ((c + 1) & 1) * SA_WORDS);
        const uint32_t* A = sA + (c & 1) * SA_WORDS;
        const uint32_t* Bc = sB + c * 32 * LDB;

        #pragma unroll
        for (int ks = 0; ks < 4; ks++) {
            int k0 = ks * 8;
            uint32_t afr[2][4];
            #pragma unroll
            for (int mt = 0; mt < 2; mt++) {
                int rb = wrb + mt * 16 + g;
                afr[mt][0] = A[rb * LDA + k0 + tg];
                afr[mt][1] = A[(rb + 8) * LDA + k0 + tg];
                afr[mt][2] = A[rb * LDA + k0 + tg + 4];
                afr[mt][3] = A[(rb + 8) * LDA + k0 + tg + 4];
            }
            #pragma unroll
            for (int nt = 0; nt < 8; nt++) {
                uint32_t bfr[2];
                int ncol = wcb + nt * 8 + g;
                bfr[0] = Bc[(k0 + tg) * LDB + ncol];
                bfr[1] = Bc[(k0 + tg + 4) * LDB + ncol];
                mma_tf32(acc[0][nt], afr[0], bfr);
                mma_tf32(acc[1][nt], afr[1], bfr);
            }
        }
        __syncthreads();
    }

    #pragma unroll
    for (int mt = 0; mt < 2; mt++) {
        int r0 = tileBase + wrb + mt * 16 + g;
        int r1 = r0 + 8;
        #pragma unroll
        for (int nt = 0; nt < 8; nt++) {
            int col = wcb + nt * 8 + tg * 2;
            float2 bb = *reinterpret_cast<const float2*>(bias + col);
            if (r0 < N_NODES) {
                float2 o;
                o.x = fmaxf(acc[mt][nt][0] + bb.x, 0.f);
                o.y = fmaxf(acc[mt][nt][1] + bb.y, 0.f);
                *reinterpret_cast<float2*>(out + r0 * D + col) = o;
            }
            if (r1 < N_NODES) {
                float2 o;
                o.x = fmaxf(acc[mt][nt][2] + bb.x, 0.f);
                o.y = fmaxf(acc[mt][nt][3] + bb.y, 0.f);
                *reinterpret_cast<float2*>(out + r1 * D + col) = o;
            }
        }
    }
}

// ---------------------------------------------------------------------------
extern "C" void kernel_launch(void* const* d_in, const int* in_sizes, int n_in,
                              void* d_out, int out_size) {
    const float* h     = (const float*)d_in[0];
    const float* r     = (const float*)d_in[1];
    const float* norm  = (const float*)d_in[2];
    const int*   src   = (const int*)d_in[3];
    const int*   dst   = (const int*)d_in[4];
    const int*   rel   = (const int*)d_in[5];
    const float* W_msg = (const float*)d_in[6];
    const float* W     = (const float*)d_in[7];
    const float* b     = (const float*)d_in[8];
    float* out = (float*)d_out;

    // fused prep: fp16 mirrors, dst histogram + per-edge rank, desc reset
    k_prep_hist<<<(PREP_T + 255) / 256, 256>>>(h, norm, dst, r);

    // single-pass scan (decoupled block aggregates)
    k_scan<<<N_CHUNKS, SCAN_T>>>();

    // CSR fill: atomic-free (g_off + precomputed rank)
    k_fill<<<(N_EDGES / 2 + 255) / 256, 256>>>(src, dst, rel);

    // gather: half-warp per edge, uint4 fp16 loads
    k_gather<<<(N_NODES * 32 + 255) / 256, 256>>>(norm);

    // tf32 mma.sync GEMM + epilogue
    cudaFuncSetAttribute(k_gemm_tc, cudaFuncAttributeMaxDynamicSharedMemorySize, SMEM_TC);
    k_gemm_tc<<<(N_NODES + 127) / 128, 256, SMEM_TC>>>(h, norm, W, W_msg, b, out);
}

// round 15
// speedup vs baseline: 1.1541x; 1.0280x over previous
#include <cuda_runtime.h>
#include <cuda_fp16.h>
#include <cstdint>

#define N_NODES 50000
#define N_EDGES 800000
#define N_RELS  200
#define D       128
#define D4      (D/4)

#define SCAN_T   1024
#define N_CHUNKS ((N_NODES + SCAN_T - 1) / SCAN_T)   // 49

// Scratch (allocation-free rule: __device__ globals)
__device__ __half    g_hnh[N_NODES * D];   // fp16 h*norm (gather operand)
__device__ __half    g_rh[N_RELS * D];     // fp16 mirror of r
__device__ float     g_agg[N_NODES * D];   // norm * segment_sum(hn[src]-r[rel], dst)
__device__ int       g_cnt[N_NODES];       // per-dst degree (zero at entry; k_scan resets)
__device__ int       g_off[N_NODES + 1];   // CSR offsets
__device__ int       g_rank[N_EDGES];      // edge rank within its dst bucket (from prep)
__device__ int       g_ekey[N_EDGES];      // packed (src<<8)|rel, bucketed by dst
__device__ unsigned  g_desc[64];           // block aggregates (bit31=valid); prep resets

// ---------------------------------------------------------------------------
// tf32 helpers (baseline PTX, no 'a' features)
// ---------------------------------------------------------------------------
__device__ __forceinline__ uint32_t f2tf32(float f) {
    uint32_t t;
    asm("cvt.rna.tf32.f32 %0, %1;" : "=r"(t) : "f"(f));
    return t;
}
__device__ __forceinline__ void mma_tf32(float* c, const uint32_t* a, const uint32_t* b) {
    asm volatile(
        "mma.sync.aligned.m16n8k8.row.col.f32.tf32.tf32.f32 "
        "{%0,%1,%2,%3}, {%4,%5,%6,%7}, {%8,%9}, {%0,%1,%2,%3};"
        : "+f"(c[0]), "+f"(c[1]), "+f"(c[2]), "+f"(c[3])
        : "r"(a[0]), "r"(a[1]), "r"(a[2]), "r"(a[3]), "r"(b[0]), "r"(b[1]));
}
__device__ __forceinline__ uint32_t pack_h2(float a, float b) {
    __half2 h = __floats2half2_rn(a, b);
    return *reinterpret_cast<uint32_t*>(&h);
}

// ---------------------------------------------------------------------------
// Kernel 1 (fused): hnh = fp16(h*norm); r -> fp16; dst histogram + edge RANK.
// g_cnt zero at entry (static init; k_scan restores each run).
// ---------------------------------------------------------------------------
#define PREP_T (N_NODES * D4 / 2)   // 800,000 threads == N_EDGES

__global__ void k_prep_hist(const float* __restrict__ h,
                            const float* __restrict__ norm,
                            const int*   __restrict__ dst,
                            const float* __restrict__ r) {
    int i = blockIdx.x * blockDim.x + threadIdx.x;
    if (i >= PREP_T) return;
    if (i < 64) g_desc[i] = 0;                       // reset scan descriptors
    g_rank[i] = atomicAdd(&g_cnt[__ldg(dst + i)], 1); // rank within dst bucket

    if (i < N_RELS * D4) {
        float4 rv = __ldg(reinterpret_cast<const float4*>(r) + i);
        uint2 u;
        u.x = pack_h2(rv.x, rv.y);
        u.y = pack_h2(rv.z, rv.w);
        reinterpret_cast<uint2*>(g_rh)[i] = u;
    }

    const float4* h4 = reinterpret_cast<const float4*>(h);
    uint2* o2 = reinterpret_cast<uint2*>(g_hnh);
    int j0 = i, j1 = i + PREP_T;
    float4 v0 = h4[j0];
    float4 v1 = h4[j1];
    float n0 = __ldg(norm + j0 / D4);
    float n1 = __ldg(norm + j1 / D4);
    uint2 u0, u1;
    u0.x = pack_h2(v0.x * n0, v0.y * n0);
    u0.y = pack_h2(v0.z * n0, v0.w * n0);
    u1.x = pack_h2(v1.x * n1, v1.y * n1);
    u1.y = pack_h2(v1.z * n1, v1.w * n1);
    o2[j0] = u0;
    o2[j1] = u1;
}

// ---------------------------------------------------------------------------
// Kernel 2: single-pass scan, 49 co-resident blocks, decoupled lookback.
// Resets g_cnt. Writes g_off + sentinel.
// ---------------------------------------------------------------------------
__global__ __launch_bounds__(SCAN_T, 1)
void k_scan() {
    __shared__ int s[SCAN_T];
    __shared__ int s2[64];
    __shared__ int s_prefix;
    const int tid = threadIdx.x;
    const int b = blockIdx.x;
    const int idx = b * SCAN_T + tid;

    int v = (idx < N_NODES) ? g_cnt[idx] : 0;
    if (idx < N_NODES) g_cnt[idx] = 0;       // restore invariant (coalesced)
    s[tid] = v;
    __syncthreads();
    #pragma unroll
    for (int ofs = 1; ofs < SCAN_T; ofs <<= 1) {
        int t = (tid >= ofs) ? s[tid - ofs] : 0;
        __syncthreads();
        s[tid] += t;
        __syncthreads();
    }

    if (tid == SCAN_T - 1)
        *reinterpret_cast<volatile unsigned*>(&g_desc[b]) = 0x80000000u | (unsigned)s[tid];

    if (tid < b) {
        unsigned u;
        do {
            u = *reinterpret_cast<volatile unsigned*>(&g_desc[tid]);
        } while (!(u & 0x80000000u));
        s2[tid] = (int)(u & 0x7FFFFFFFu);
    }
    __syncthreads();
    if (tid == 0) {
        int p = 0;
        for (int j = 0; j < b; j++) p += s2[j];
        s_prefix = p;
    }
    __syncthreads();

    if (idx < N_NODES) g_off[idx] = s_prefix + s[tid] - v;   // exclusive prefix
    if (b == 0 && tid == 0) g_off[N_NODES] = N_EDGES;
}

// ---------------------------------------------------------------------------
// Kernel 3: CSR fill — NO ATOMICS: pos = g_off[dst] + rank (rank from prep).
// Pure streaming loads + one scattered STG per edge.
// ---------------------------------------------------------------------------
__global__ void k_fill(const int* __restrict__ src,
                       const int* __restrict__ dst,
                       const int* __restrict__ rel) {
    int t = blockIdx.x * blockDim.x + threadIdx.x;
    int e0 = t * 2, e1 = t * 2 + 1;
    if (e0 >= N_EDGES) return;
    int d0 = __ldg(dst + e0);
    int d1 = __ldg(dst + e1);
    int p0 = __ldg(g_off + d0) + __ldg(g_rank + e0);
    int p1 = __ldg(g_off + d1) + __ldg(g_rank + e1);
    g_ekey[p0] = (__ldg(src + e0) << 8) | __ldg(rel + e0);
    g_ekey[p1] = (__ldg(src + e1) << 8) | __ldg(rel + e1);
}

// ---------------------------------------------------------------------------
// Kernel 4: gather — HALF-WARP per edge (2 edges/warp-step), uint4 fp16 loads.
// 16 lanes x 16B = one 256B row. Issue count per edge ~halved vs full-warp.
// Keys prefetched coalesced (lane l reads key base+l), broadcast via shfl.
// ---------------------------------------------------------------------------
__device__ __forceinline__ void acc8(float* a, uint4 u, uint4 w) {
    __half2 d0 = __hsub2(*reinterpret_cast<__half2*>(&u.x),
                         *reinterpret_cast<__half2*>(&w.x));
    __half2 d1 = __hsub2(*reinterpret_cast<__half2*>(&u.y),
                         *reinterpret_cast<__half2*>(&w.y));
    __half2 d2 = __hsub2(*reinterpret_cast<__half2*>(&u.z),
                         *reinterpret_cast<__half2*>(&w.z));
    __half2 d3 = __hsub2(*reinterpret_cast<__half2*>(&u.w),
                         *reinterpret_cast<__half2*>(&w.w));
    float2 f0 = __half22float2(d0);
    float2 f1 = __half22float2(d1);
    float2 f2 = __half22float2(d2);
    float2 f3 = __half22float2(d3);
    a[0] += f0.x; a[1] += f0.y; a[2] += f1.x; a[3] += f1.y;
    a[4] += f2.x; a[5] += f2.y; a[6] += f3.x; a[7] += f3.y;
}

__global__ void k_gather(const float* __restrict__ norm) {
    int warp = (blockIdx.x * blockDim.x + threadIdx.x) >> 5;
    int lane = threadIdx.x & 31;
    if (warp >= N_NODES) return;
    const int hw  = lane >> 4;     // half-warp id (0/1)
    const int sub = lane & 15;     // lane within half-warp

    int e0 = __ldg(g_off + warp);
    int e1 = __ldg(g_off + warp + 1);

    const uint4* hh = reinterpret_cast<const uint4*>(g_hnh);  // row stride 16
    const uint4* rr = reinterpret_cast<const uint4*>(g_rh);

    float acc[8];
    #pragma unroll
    for (int i = 0; i < 8; i++) acc[i] = 0.f;

    for (int base = e0; base < e1; base += 32) {
        int n = min(32, e1 - base);
        int key = 0;
        if (base + lane < e1) key = __ldg(g_ekey + base + lane);   // coalesced

        int j = 0;
        // 8 edges per iteration (4 pairs), MLP=4 per lane
        for (; j + 8 <= n; j += 8) {
            uint4 u[4], w[4];
            #pragma unroll
            for (int t = 0; t < 4; t++) {
                int k = __shfl_sync(0xffffffffu, key, j + 2 * t + hw);
                u[t] = __ldcg(hh + (k >> 8) * 16 + sub);
                w[t] = __ldg(rr + (k & 255) * 16 + sub);
            }
            #pragma unroll
            for (int t = 0; t < 4; t++) acc8(acc, u[t], w[t]);
        }
        // pair remainder
        for (; j + 2 <= n; j += 2) {
            int k = __shfl_sync(0xffffffffu, key, j + hw);
            uint4 u = __ldcg(hh + (k >> 8) * 16 + sub);
            uint4 w = __ldg(rr + (k & 255) * 16 + sub);
            acc8(acc, u, w);
        }
        // odd single edge: first half-warp only
        if (j < n) {
            int k = __shfl_sync(0xffffffffu, key, j);
            if (hw == 0) {
                uint4 u = __ldcg(hh + (k >> 8) * 16 + sub);
                uint4 w = __ldg(rr + (k & 255) * 16 + sub);
                acc8(acc, u, w);
            }
        }
    }

    // combine the two half-warps (cols identical across halves)
    #pragma unroll
    for (int i = 0; i < 8; i++)
        acc[i] += __shfl_down_sync(0xffffffffu, acc[i], 16);

    if (hw == 0) {
        float nm = __ldg(norm + warp);
        float4 o0, o1;
        o0.x = acc[0] * nm; o0.y = acc[1] * nm;
        o0.z = acc[2] * nm; o0.w = acc[3] * nm;
        o1.x = acc[4] * nm; o1.y = acc[5] * nm;
        o1.z = acc[6] * nm; o1.w = acc[7] * nm;
        float4* op = reinterpret_cast<float4*>(g_agg) + warp * 32 + sub * 2;
        op[0] = o0;
        op[1] = o1;
    }
}

// ---------------------------------------------------------------------------
// Kernel 5: tf32 mma.sync GEMM  out = relu( [h*norm | agg] @ [W ; W_msg] + b )
// ---------------------------------------------------------------------------
#define LDB 136
#define LDA 36
#define SB_WORDS (256 * LDB)
#define SA_WORDS (128 * LDA)
#define SMEM_TC  ((SB_WORDS + 2 * SA_WORDS) * 4)   // 176,128 bytes

__global__ __launch_bounds__(256, 1)
void k_gemm_tc(const float* __restrict__ h,
               const float* __restrict__ norm,
               const float* __restrict__ W,
               const float* __restrict__ W_msg,
               const float* __restrict__ bias,
               float* __restrict__ out) {
    extern __shared__ uint32_t smw[];
    uint32_t* sB = smw;                 // [256][LDB]
    uint32_t* sA = smw + SB_WORDS;      // 2 x [128][LDA]

    const int tid = threadIdx.x;
    const int wid = tid >> 5;
    const int lane = tid & 31;
    const int g  = lane >> 2;
    const int tg = lane & 3;
    const int tileBase = blockIdx.x * 128;
    const int wrb = (wid & 3) * 32;
    const int wcb = (wid >> 2) * 64;

    {
        #pragma unroll
        for (int i = tid; i < 256 * 32; i += 256) {
            int k = i >> 5, f4 = i & 31;
            const float4* srcp = (k < 128)
                ? reinterpret_cast<const float4*>(W) + k * 32 + f4
                : reinterpret_cast<const float4*>(W_msg) + (k - 128) * 32 + f4;
            float4 v = __ldg(srcp);
            uint4 t;
            t.x = f2tf32(v.x); t.y = f2tf32(v.y);
            t.z = f2tf32(v.z); t.w = f2tf32(v.w);
            *reinterpret_cast<uint4*>(sB + k * LDB + f4 * 4) = t;
        }
    }

    auto loadA = [&](int c, uint32_t* buf) {
        int kc = (c & 3) * 8;
        #pragma unroll
        for (int i = tid; i < 128 * 8; i += 256) {
            int row = i >> 3, f4 = i & 7;
            int gr = tileBase + row;
            float4 v = make_float4(0.f, 0.f, 0.f, 0.f);
            if (gr < N_NODES) {
                if (c < 4) {
                    v = __ldg(reinterpret_cast<const float4*>(h) + gr * 32 + kc + f4);
                    float nm = __ldg(norm + gr);
                    v.x *= nm; v.y *= nm; v.z *= nm; v.w *= nm;
                } else {
                    v = __ldcg(reinterpret_cast<const float4*>(g_agg) + gr * 32 + kc + f4);
                }
            }
            uint4 t;
            t.x = f2tf32(v.x); t.y = f2tf32(v.y);
            t.z = f2tf32(v.z); t.w = f2tf32(v.w);
            *reinterpret_cast<uint4*>(buf + row * LDA + f4 * 4) = t;
        }
    };

    float acc[2][8][4];
    #pragma unroll
    for (int mt = 0; mt < 2; mt++)
        #pragma unroll
        for (int nt = 0; nt < 8; nt++)
            #pragma unroll
            for (int cc = 0; cc < 4; cc++) acc[mt][nt][cc] = 0.f;

    loadA(0, sA);
    __syncthreads();

    #pragma unroll
    for (int c = 0; c < 8; c++) {
        if (c + 1 < 8) loadA(c + 1, sA + ((c + 1) & 1) * SA_WORDS);
        const uint32_t* A = sA + (c & 1) * SA_WORDS;
        const uint32_t* Bc = sB + c * 32 * LDB;

        #pragma unroll
        for (int ks = 0; ks < 4; ks++) {
            int k0 = ks * 8;
            uint32_t afr[2][4];
            #pragma unroll
            for (int mt = 0; mt < 2; mt++) {
                int rb = wrb + mt * 16 + g;
                afr[mt][0] = A[rb * LDA + k0 + tg];
                afr[mt][1] = A[(rb + 8) * LDA + k0 + tg];
                afr[mt][2] = A[rb * LDA + k0 + tg + 4];
                afr[mt][3] = A[(rb + 8) * LDA + k0 + tg + 4];
            }
            #pragma unroll
            for (int nt = 0; nt < 8; nt++) {
                uint32_t bfr[2];
                int ncol = wcb + nt * 8 + g;
                bfr[0] = Bc[(k0 + tg) * LDB + ncol];
                bfr[1] = Bc[(k0 + tg + 4) * LDB + ncol];
                mma_tf32(acc[0][nt], afr[0], bfr);
                mma_tf32(acc[1][nt], afr[1], bfr);
            }
        }
        __syncthreads();
    }

    #pragma unroll
    for (int mt = 0; mt < 2; mt++) {
        int r0 = tileBase + wrb + mt * 16 + g;
        int r1 = r0 + 8;
        #pragma unroll
        for (int nt = 0; nt < 8; nt++) {
            int col = wcb + nt * 8 + tg * 2;
            float2 bb = *reinterpret_cast<const float2*>(bias + col);
            if (r0 < N_NODES) {
                float2 o;
                o.x = fmaxf(acc[mt][nt][0] + bb.x, 0.f);
                o.y = fmaxf(acc[mt][nt][1] + bb.y, 0.f);
                *reinterpret_cast<float2*>(out + r0 * D + col) = o;
            }
            if (r1 < N_NODES) {
                float2 o;
                o.x = fmaxf(acc[mt][nt][2] + bb.x, 0.f);
                o.y = fmaxf(acc[mt][nt][3] + bb.y, 0.f);
                *reinterpret_cast<float2*>(out + r1 * D + col) = o;
            }
        }
    }
}

// ---------------------------------------------------------------------------
extern "C" void kernel_launch(void* const* d_in, const int* in_sizes, int n_in,
                              void* d_out, int out_size) {
    const float* h     = (const float*)d_in[0];
    const float* r     = (const float*)d_in[1];
    const float* norm  = (const float*)d_in[2];
    const int*   src   = (const int*)d_in[3];
    const int*   dst   = (const int*)d_in[4];
    const int*   rel   = (const int*)d_in[5];
    const float* W_msg = (const float*)d_in[6];
    const float* W     = (const float*)d_in[7];
    const float* b     = (const float*)d_in[8];
    float* out = (float*)d_out;

    // fused prep: fp16 mirrors, dst histogram + per-edge rank, desc reset
    k_prep_hist<<<(PREP_T + 255) / 256, 256>>>(h, norm, dst, r);

    // single-pass scan (decoupled block aggregates)
    k_scan<<<N_CHUNKS, SCAN_T>>>();

    // CSR fill: atomic-free (g_off + precomputed rank)
    k_fill<<<(N_EDGES / 2 + 255) / 256, 256>>>(src, dst, rel);

    // gather: half-warp per edge, uint4 fp16 loads
    k_gather<<<(N_NODES * 32 + 255) / 256, 256>>>(norm);

    // tf32 mma.sync GEMM + epilogue
    cudaFuncSetAttribute(k_gemm_tc, cudaFuncAttributeMaxDynamicSharedMemorySize, SMEM_TC);
    k_gemm_tc<<<(N_NODES + 127) / 128, 256, SMEM_TC>>>(h, norm, W, W_msg, b, out);
}